// round 2
// baseline (speedup 1.0000x reference)
#include <cuda_runtime.h>
#include <cstdint>

#define N_PTS   16384
#define THREADS 256
#define QPT     8                        // queries per thread
#define QPB     (THREADS * QPT)          // 2048 queries per block
#define QBLKS   (N_PTS / QPB)            // 8
#define TILE    512                      // targets per slice
#define SLICES  (N_PTS / TILE)           // 32

// Running "min" per query stored as key = ~bits(d) folded with atomicMax.
// d >= 0  =>  bits(d) monotone in d  =>  ~bits monotone decreasing:
//   min d  <=>  max key.   Desired init (d = +inf) is key = 0, which is the
// load-time zero-init of a __device__ global. The reduce kernel resets keys
// to 0 after consuming them, so every kernel_launch call (first, capture,
// every replay) sees the same initial state. No init kernel needed.
__device__ unsigned g_key[2][N_PTS];

// ---- packed f32x2 helpers (FFMA2 only reachable via PTX on sm_103a) ----
#define PACK2(d, lo, hi) \
    asm("mov.b64 %0, {%1,%2};" : "=l"(d) : "f"(lo), "f"(hi))
#define UNPACK2(lo, hi, s) \
    asm("mov.b64 {%0,%1}, %2;" : "=f"(lo), "=f"(hi) : "l"(s))
#define FMA2(d, a, b, c) \
    asm("fma.rn.f32x2 %0, %1, %2, %3;" : "=l"(d) : "l"(a), "l"(b), "l"(c))

__global__ __launch_bounds__(THREADS)
void chamfer_main_kernel(const float* __restrict__ state_x,
                         const float* __restrict__ target) {
    const int dir = blockIdx.z;
    const float* __restrict__ qp = (dir == 0) ? target  : state_x;
    const float* __restrict__ rp = (dir == 0) ? state_x : target;

    // Pre-duplicated target tile: each LDS.128 yields two ready-to-use
    // packed broadcast operands, zero pack MOVs in the hot loop.
    __shared__ ulonglong2 shA[TILE];  // ((x,x), (y,y))
    __shared__ ulonglong2 shB[TILE];  // ((z,z), (s,s))  s = x^2+y^2+z^2

    const int j0 = blockIdx.y * TILE;
    for (int j = threadIdx.x; j < TILE; j += THREADS) {
        float x = rp[(j0 + j) * 3 + 0];
        float y = rp[(j0 + j) * 3 + 1];
        float z = rp[(j0 + j) * 3 + 2];
        float s = x * x + y * y + z * z;
        unsigned long long xx, yy, zz, ss;
        PACK2(xx, x, x);
        PACK2(yy, y, y);
        PACK2(zz, z, z);
        PACK2(ss, s, s);
        shA[j] = make_ulonglong2(xx, yy);
        shB[j] = make_ulonglong2(zz, ss);
    }
    __syncthreads();

    // 8 queries per thread as 4 packed f32x2 lanes.
    const int qbase = blockIdx.x * QPB + threadIdx.x;
    unsigned long long nax[QPT / 2], nay[QPT / 2], naz[QPT / 2];
    float a2[QPT], m[QPT];

    #pragma unroll
    for (int p = 0; p < QPT / 2; p++) {
        int qi0 = qbase + (2 * p + 0) * THREADS;
        int qi1 = qbase + (2 * p + 1) * THREADS;
        float x0 = qp[qi0 * 3 + 0], y0 = qp[qi0 * 3 + 1], z0 = qp[qi0 * 3 + 2];
        float x1 = qp[qi1 * 3 + 0], y1 = qp[qi1 * 3 + 1], z1 = qp[qi1 * 3 + 2];
        a2[2 * p + 0] = x0 * x0 + y0 * y0 + z0 * z0;
        a2[2 * p + 1] = x1 * x1 + y1 * y1 + z1 * z1;
        PACK2(nax[p], -2.0f * x0, -2.0f * x1);
        PACK2(nay[p], -2.0f * y0, -2.0f * y1);
        PACK2(naz[p], -2.0f * z0, -2.0f * z1);
        m[2 * p + 0] = __int_as_float(0x7f800000);
        m[2 * p + 1] = __int_as_float(0x7f800000);
    }

    // Hot loop per j (8 pairs): 2 LDS.128 + 12 FFMA2 + 8 FMNMX (+ loop ovh).
    #pragma unroll 4
    for (int j = 0; j < TILE; j++) {
        ulonglong2 t1 = shA[j];   // (xx, yy)
        ulonglong2 t2 = shB[j];   // (zz, ss)
        #pragma unroll
        for (int p = 0; p < QPT / 2; p++) {
            unsigned long long e;
            FMA2(e, nax[p], t1.x, t2.y);   // -2ax*bx + b^2
            FMA2(e, nay[p], t1.y, e);
            FMA2(e, naz[p], t2.x, e);
            float elo, ehi;
            UNPACK2(elo, ehi, e);          // reg-pair alias; ptxas coalesces
            m[2 * p + 0] = fminf(m[2 * p + 0], elo);
            m[2 * p + 1] = fminf(m[2 * p + 1], ehi);
        }
    }

    // Fold across slices: d = max(a2 + min_e, 0); key = ~bits(d), atomicMax.
    #pragma unroll
    for (int i = 0; i < QPT; i++) {
        int qi = qbase + i * THREADS;
        float d = fmaxf(a2[i] + m[i], 0.0f);
        atomicMax(&g_key[dir][qi], ~__float_as_uint(d));
    }
}

__global__ __launch_bounds__(1024)
void chamfer_reduce_kernel(float* __restrict__ out) {
    __shared__ float red[1024];
    const int tid = threadIdx.x;
    uint4* g4 = (uint4*)g_key;    // 32768 keys = 8192 uint4
    float s = 0.0f;
    #pragma unroll
    for (int k = 0; k < 8; k++) {
        int i = tid + k * 1024;
        uint4 v = g4[i];
        s += sqrtf(__uint_as_float(~v.x)) + sqrtf(__uint_as_float(~v.y)) +
             sqrtf(__uint_as_float(~v.z)) + sqrtf(__uint_as_float(~v.w));
        g4[i] = make_uint4(0u, 0u, 0u, 0u);   // reset for next call/replay
    }
    red[tid] = s;
    __syncthreads();
    #pragma unroll
    for (int off = 512; off > 0; off >>= 1) {
        if (tid < off) red[tid] += red[tid + off];
        __syncthreads();
    }
    if (tid == 0)
        // loss = (mean(sqrt(d1)) + mean(sqrt(d2))) * 0.5 * 10 = sum * 5 / N
        out[0] = red[0] * (5.0f / (float)N_PTS);
}

extern "C" void kernel_launch(void* const* d_in, const int* in_sizes, int n_in,
                              void* d_out, int out_size) {
    const float* state_x = (const float*)d_in[0];
    const float* target  = (const float*)d_in[1];

    dim3 grid(QBLKS, SLICES, 2);
    chamfer_main_kernel<<<grid, THREADS>>>(state_x, target);

    chamfer_reduce_kernel<<<1, 1024>>>((float*)d_out);
}